// round 1
// baseline (speedup 1.0000x reference)
#include <cuda_runtime.h>

#define N_NODES 50000
#define N_EDGES 800000
#define NODE_IN 256
#define EDGE_IN 64
#define HID 128
#define OUT_DIM 16
#define EPS 1e-5f

// Scratch (static device globals — no runtime allocation)
__device__ float g_hv[(size_t)N_NODES * HID];  // LN(GELU(node_feats @ W_node))
__device__ float g_h [(size_t)N_NODES * HID];  // segment-sum accumulator

__device__ __forceinline__ float gelu_exact(float x) {
    return 0.5f * x * (1.0f + erff(x * 0.7071067811865476f));
}

__device__ __forceinline__ void red_add_v4(float* p, float a, float b, float c, float d) {
    asm volatile("red.global.add.v4.f32 [%0], {%1,%2,%3,%4};"
                 :: "l"(p), "f"(a), "f"(b), "f"(c), "f"(d) : "memory");
}

// ---------------------------------------------------------------------------
// Kernel 1: hv = LayerNorm(GELU(node_feats @ W_node))
// 16 nodes per 128-thread block; thread = output column.
// ---------------------------------------------------------------------------
__global__ __launch_bounds__(128) void node_proj_kernel(
    const float* __restrict__ nf, const float* __restrict__ Wn,
    const float* __restrict__ g, const float* __restrict__ b)
{
    __shared__ float sNF[16 * NODE_IN];   // 16 KB
    __shared__ float2 sPart[4][16];
    __shared__ float2 sStat[16];

    const int tid = threadIdx.x;
    const int n0  = blockIdx.x * 16;

    // stage 16 node rows (4096 floats) coalesced
    {
        const float4* gv = (const float4*)(nf + (size_t)n0 * NODE_IN);
        float4* sv = (float4*)sNF;
        #pragma unroll
        for (int i = tid; i < 1024; i += 128) sv[i] = gv[i];
    }
    __syncthreads();

    const int c = tid;
    float acc[16];
    #pragma unroll
    for (int n = 0; n < 16; n++) acc[n] = 0.f;

    const float4* sNFv = (const float4*)sNF;
    #pragma unroll 4
    for (int k4 = 0; k4 < NODE_IN / 4; k4++) {
        const float w0 = Wn[(4*k4+0)*HID + c];
        const float w1 = Wn[(4*k4+1)*HID + c];
        const float w2 = Wn[(4*k4+2)*HID + c];
        const float w3 = Wn[(4*k4+3)*HID + c];
        #pragma unroll
        for (int n = 0; n < 16; n++) {
            const float4 a = sNFv[n*(NODE_IN/4) + k4];
            acc[n] += a.x*w0 + a.y*w1 + a.z*w2 + a.w*w3;
        }
    }

    #pragma unroll
    for (int n = 0; n < 16; n++) acc[n] = gelu_exact(acc[n]);

    // per-node mean/var across 128 columns (warp reduce + cross-warp via smem)
    const int w = tid >> 5, lane = tid & 31;
    #pragma unroll
    for (int n = 0; n < 16; n++) {
        float s = acc[n], s2 = acc[n]*acc[n];
        #pragma unroll
        for (int off = 16; off; off >>= 1) {
            s  += __shfl_xor_sync(0xffffffffu, s,  off);
            s2 += __shfl_xor_sync(0xffffffffu, s2, off);
        }
        if (lane == 0) sPart[w][n] = make_float2(s, s2);
    }
    __syncthreads();
    if (tid < 16) {
        float s = 0.f, s2 = 0.f;
        #pragma unroll
        for (int ww = 0; ww < 4; ww++) { s += sPart[ww][tid].x; s2 += sPart[ww][tid].y; }
        const float mu  = s * (1.f / HID);
        const float var = s2 * (1.f / HID) - mu * mu;
        sStat[tid] = make_float2(mu, rsqrtf(var + EPS));
    }
    __syncthreads();

    const float gc = g[c], bc = b[c];
    #pragma unroll
    for (int n = 0; n < 16; n++) {
        const float2 st = sStat[n];
        g_hv[(size_t)(n0 + n) * HID + c] = (acc[n] - st.x) * st.y * gc + bc;
    }
}

// ---------------------------------------------------------------------------
// Kernel 2: zero the segment-sum accumulator
// ---------------------------------------------------------------------------
__global__ void zero_h_kernel() {
    float4* p = (float4*)g_h;
    const int n4 = (N_NODES * HID) / 4;  // 1.6M
    const float4 z = make_float4(0.f, 0.f, 0.f, 0.f);
    for (int i = blockIdx.x * blockDim.x + threadIdx.x; i < n4;
         i += gridDim.x * blockDim.x)
        p[i] = z;
}

// ---------------------------------------------------------------------------
// Kernel 3 (hot): per edge: z = ef @ W_edge ; he = exp(LN(z)) ;
//                 red_add(h[dst], hv[src] * he)
// W_edge in smem (32 KB). 8 edges per warp, lane owns cols [4*lane, 4*lane+3].
// ---------------------------------------------------------------------------
__global__ __launch_bounds__(128) void edge_kernel(
    const float* __restrict__ ef, const int* __restrict__ src,
    const int* __restrict__ dst,  const float* __restrict__ We,
    const float* __restrict__ g,  const float* __restrict__ b)
{
    __shared__ float sW[EDGE_IN * HID];      // 32 KB
    __shared__ float sEF[4][8 * EDGE_IN];    // 8 KB (per-warp edge staging)

    const int tid = threadIdx.x;
    #pragma unroll
    for (int i = tid; i < EDGE_IN * HID; i += 128) sW[i] = We[i];
    __syncthreads();

    const int w = tid >> 5, lane = tid & 31;
    const float4 ge = *(const float4*)(g + 4*lane);
    const float4 be = *(const float4*)(b + 4*lane);
    const float4* sWv  = (const float4*)sW;
    float4* sEFv = (float4*)sEF[w];

    const int nTiles = (N_EDGES + 7) >> 3;
    const int nwarp  = gridDim.x * 4;
    for (int t = blockIdx.x * 4 + w; t < nTiles; t += nwarp) {
        const int e0 = t * 8;
        __syncwarp();
        if (e0 + 8 <= N_EDGES) {
            const float4* egv = (const float4*)(ef + (size_t)e0 * EDGE_IN);
            #pragma unroll
            for (int r = 0; r < 4; r++) sEFv[lane + 32*r] = egv[lane + 32*r];
        } else {
            for (int i = lane; i < 128; i += 32) {
                const int e = e0 + (i >> 4);
                sEFv[i] = (e < N_EDGES)
                    ? ((const float4*)ef)[(size_t)e * (EDGE_IN/4) + (i & 15)]
                    : make_float4(0.f, 0.f, 0.f, 0.f);
            }
        }
        __syncwarp();

        float4 acc[8];
        #pragma unroll
        for (int e = 0; e < 8; e++) acc[e] = make_float4(0.f, 0.f, 0.f, 0.f);

        #pragma unroll 4
        for (int k4 = 0; k4 < EDGE_IN / 4; k4++) {
            const float4 w0 = sWv[(4*k4+0)*32 + lane];
            const float4 w1 = sWv[(4*k4+1)*32 + lane];
            const float4 w2 = sWv[(4*k4+2)*32 + lane];
            const float4 w3 = sWv[(4*k4+3)*32 + lane];
            #pragma unroll
            for (int e = 0; e < 8; e++) {
                const float4 a = sEFv[e*(EDGE_IN/4) + k4];  // broadcast
                acc[e].x += a.x*w0.x + a.y*w1.x + a.z*w2.x + a.w*w3.x;
                acc[e].y += a.x*w0.y + a.y*w1.y + a.z*w2.y + a.w*w3.y;
                acc[e].z += a.x*w0.z + a.y*w1.z + a.z*w2.z + a.w*w3.z;
                acc[e].w += a.x*w0.w + a.y*w1.w + a.z*w2.w + a.w*w3.w;
            }
        }

        const int eMax = min(8, N_EDGES - e0);
        for (int e = 0; e < eMax; e++) {
            const float4 x = acc[e];
            float s  = x.x + x.y + x.z + x.w;
            float s2 = x.x*x.x + x.y*x.y + x.z*x.z + x.w*x.w;
            #pragma unroll
            for (int off = 16; off; off >>= 1) {
                s  += __shfl_xor_sync(0xffffffffu, s,  off);
                s2 += __shfl_xor_sync(0xffffffffu, s2, off);
            }
            const float mu   = s * (1.f / HID);
            const float rstd = rsqrtf(s2 * (1.f / HID) - mu * mu + EPS);
            const int sv = src[e0 + e], dv = dst[e0 + e];
            const float4 hvv = *(const float4*)(g_hv + (size_t)sv * HID + 4*lane);
            const float m0 = hvv.x * __expf((x.x - mu) * rstd * ge.x + be.x);
            const float m1 = hvv.y * __expf((x.y - mu) * rstd * ge.y + be.y);
            const float m2 = hvv.z * __expf((x.z - mu) * rstd * ge.z + be.z);
            const float m3 = hvv.w * __expf((x.w - mu) * rstd * ge.w + be.w);
            red_add_v4(g_h + (size_t)dv * HID + 4*lane, m0, m1, m2, m3);
        }
    }
}

// ---------------------------------------------------------------------------
// Kernel 4: out = LayerNorm(GELU(h @ W_out))
// 16 nodes per 256-thread block; thread = (node_local, out_col).
// ---------------------------------------------------------------------------
__global__ __launch_bounds__(256) void out_kernel(
    const float* __restrict__ Wo, const float* __restrict__ g,
    const float* __restrict__ b,  float* __restrict__ out)
{
    __shared__ float sH [16 * HID];        // 8 KB
    __shared__ float sWo[HID * OUT_DIM];   // 8 KB

    const int tid = threadIdx.x;
    const int n0  = blockIdx.x * 16;
    {
        const float4* hv4 = (const float4*)(g_h + (size_t)n0 * HID);
        float4* sH4 = (float4*)sH;
        #pragma unroll
        for (int i = tid; i < 512; i += 256) sH4[i] = hv4[i];
        const float4* wv4 = (const float4*)Wo;
        float4* sW4 = (float4*)sWo;
        #pragma unroll
        for (int i = tid; i < 512; i += 256) sW4[i] = wv4[i];
    }
    __syncthreads();

    const int n = tid >> 4, c = tid & 15;
    float acc = 0.f;
    const float4* sHn = (const float4*)(sH + n * HID);
    #pragma unroll 4
    for (int k4 = 0; k4 < HID / 4; k4++) {
        const float4 a = sHn[k4];
        acc += a.x * sWo[(4*k4+0)*OUT_DIM + c];
        acc += a.y * sWo[(4*k4+1)*OUT_DIM + c];
        acc += a.z * sWo[(4*k4+2)*OUT_DIM + c];
        acc += a.w * sWo[(4*k4+3)*OUT_DIM + c];
    }

    const float v = gelu_exact(acc);
    float s = v, s2 = v * v;
    #pragma unroll
    for (int off = 8; off; off >>= 1) {
        s  += __shfl_xor_sync(0xffffffffu, s,  off);
        s2 += __shfl_xor_sync(0xffffffffu, s2, off);
    }
    const float mu   = s * (1.f / OUT_DIM);
    const float rstd = rsqrtf(s2 * (1.f / OUT_DIM) - mu * mu + EPS);
    out[(size_t)(n0 + n) * OUT_DIM + c] = (v - mu) * rstd * g[c] + b[c];
}

// ---------------------------------------------------------------------------
extern "C" void kernel_launch(void* const* d_in, const int* in_sizes, int n_in,
                              void* d_out, int out_size) {
    const float* node_feats = (const float*)d_in[0];
    const float* edge_feats = (const float*)d_in[1];
    const int*   src        = (const int*)  d_in[2];
    const int*   dst        = (const int*)  d_in[3];
    const float* W_node     = (const float*)d_in[4];
    const float* g_node     = (const float*)d_in[5];
    const float* b_node     = (const float*)d_in[6];
    const float* W_edge     = (const float*)d_in[7];
    const float* g_edge     = (const float*)d_in[8];
    const float* b_edge     = (const float*)d_in[9];
    const float* W_out      = (const float*)d_in[10];
    const float* g_out      = (const float*)d_in[11];
    const float* b_out      = (const float*)d_in[12];
    float* out = (float*)d_out;

    node_proj_kernel<<<N_NODES / 16, 128>>>(node_feats, W_node, g_node, b_node);
    zero_h_kernel<<<2048, 256>>>();
    edge_kernel<<<740, 128>>>(edge_feats, src, dst, W_edge, g_edge, b_edge);
    out_kernel<<<N_NODES / 16, 256>>>(W_out, g_out, b_out, out);
}

// round 2
// speedup vs baseline: 1.5809x; 1.5809x over previous
#include <cuda_runtime.h>
#include <cuda_bf16.h>

#define N_NODES 50000
#define N_EDGES 800000
#define NODE_IN 256
#define EDGE_IN 64
#define HID 128
#define OUT_DIM 16
#define EPS 1e-5f

// Scratch (static device globals — no runtime allocation)
__device__ float g_hv[(size_t)N_NODES * HID];  // LN(GELU(node@Wn)) * exp(b_edge)
__device__ float g_h [(size_t)N_NODES * HID];  // segment-sum accumulator

__device__ __forceinline__ float gelu_exact(float x) {
    return 0.5f * x * (1.0f + erff(x * 0.7071067811865476f));
}

__device__ __forceinline__ void red_add_v2(float* p, float a, float b) {
    asm volatile("red.global.add.v2.f32 [%0], {%1,%2};"
                 :: "l"(p), "f"(a), "f"(b) : "memory");
}

__device__ __forceinline__ unsigned pack_bf2(float x, float y) {
    __nv_bfloat162 t = __floats2bfloat162_rn(x, y);
    return *reinterpret_cast<unsigned*>(&t);
}

// split a float2 into bf16-hi pair and bf16-lo (residual) pair, packed .b32
__device__ __forceinline__ void split2(float2 v, unsigned& hi, unsigned& lo) {
    float hx = __bfloat162float(__float2bfloat16_rn(v.x));
    float hy = __bfloat162float(__float2bfloat16_rn(v.y));
    hi = pack_bf2(hx, hy);
    lo = pack_bf2(v.x - hx, v.y - hy);
}

__device__ __forceinline__ void mma_bf16(float d[4],
                                         unsigned a0, unsigned a1, unsigned a2, unsigned a3,
                                         unsigned b0, unsigned b1) {
    asm volatile(
        "mma.sync.aligned.m16n8k16.row.col.f32.bf16.bf16.f32 "
        "{%0,%1,%2,%3}, {%4,%5,%6,%7}, {%8,%9}, {%0,%1,%2,%3};"
        : "+f"(d[0]), "+f"(d[1]), "+f"(d[2]), "+f"(d[3])
        : "r"(a0), "r"(a1), "r"(a2), "r"(a3), "r"(b0), "r"(b1));
}

// ---------------------------------------------------------------------------
// Kernel 1: hv = LayerNorm(GELU(node_feats @ W_node)) * exp(b_edge)
//           Also zeroes this block's 16 rows of the g_h accumulator.
// 16 nodes per 128-thread block; thread = output column.
// ---------------------------------------------------------------------------
__global__ __launch_bounds__(128) void node_proj_kernel(
    const float* __restrict__ nf, const float* __restrict__ Wn,
    const float* __restrict__ g, const float* __restrict__ b,
    const float* __restrict__ b_edge)
{
    __shared__ float sNF[16 * NODE_IN];   // 16 KB
    __shared__ float2 sPart[4][16];
    __shared__ float2 sStat[16];

    const int tid = threadIdx.x;
    const int n0  = blockIdx.x * 16;

    // zero this block's slice of the accumulator (16 rows x 128 = 512 float4)
    {
        float4* hz = (float4*)(g_h + (size_t)n0 * HID);
        const float4 z4 = make_float4(0.f, 0.f, 0.f, 0.f);
        #pragma unroll
        for (int i = tid; i < 512; i += 128) hz[i] = z4;
    }

    // stage 16 node rows (4096 floats) coalesced
    {
        const float4* gv = (const float4*)(nf + (size_t)n0 * NODE_IN);
        float4* sv = (float4*)sNF;
        #pragma unroll
        for (int i = tid; i < 1024; i += 128) sv[i] = gv[i];
    }
    __syncthreads();

    const int c = tid;
    float acc[16];
    #pragma unroll
    for (int n = 0; n < 16; n++) acc[n] = 0.f;

    const float4* sNFv = (const float4*)sNF;
    #pragma unroll 4
    for (int k4 = 0; k4 < NODE_IN / 4; k4++) {
        const float w0 = Wn[(4*k4+0)*HID + c];
        const float w1 = Wn[(4*k4+1)*HID + c];
        const float w2 = Wn[(4*k4+2)*HID + c];
        const float w3 = Wn[(4*k4+3)*HID + c];
        #pragma unroll
        for (int n = 0; n < 16; n++) {
            const float4 a = sNFv[n*(NODE_IN/4) + k4];
            acc[n] += a.x*w0 + a.y*w1 + a.z*w2 + a.w*w3;
        }
    }

    #pragma unroll
    for (int n = 0; n < 16; n++) acc[n] = gelu_exact(acc[n]);

    const int w = tid >> 5, lane = tid & 31;
    #pragma unroll
    for (int n = 0; n < 16; n++) {
        float s = acc[n], s2 = acc[n]*acc[n];
        #pragma unroll
        for (int off = 16; off; off >>= 1) {
            s  += __shfl_xor_sync(0xffffffffu, s,  off);
            s2 += __shfl_xor_sync(0xffffffffu, s2, off);
        }
        if (lane == 0) sPart[w][n] = make_float2(s, s2);
    }
    __syncthreads();
    if (tid < 16) {
        float s = 0.f, s2 = 0.f;
        #pragma unroll
        for (int ww = 0; ww < 4; ww++) { s += sPart[ww][tid].x; s2 += sPart[ww][tid].y; }
        const float mu  = s * (1.f / HID);
        const float var = s2 * (1.f / HID) - mu * mu;
        sStat[tid] = make_float2(mu, rsqrtf(var + EPS));
    }
    __syncthreads();

    const float gc = g[c], bc = b[c];
    const float ebe = __expf(b_edge[c]);   // fold exp(b_edge) into hv
    #pragma unroll
    for (int n = 0; n < 16; n++) {
        const float2 st = sStat[n];
        g_hv[(size_t)(n0 + n) * HID + c] =
            ((acc[n] - st.x) * st.y * gc + bc) * ebe;
    }
}

// ---------------------------------------------------------------------------
// Kernel 2 (hot): per 16-edge warp tile:
//   z = ef @ W_edge via mma.sync bf16 3-term split (~fp32 accuracy)
//   he = exp(LN(z)*g)  (b folded into hv);  red.add(h[dst], hv[src]*he)
// ---------------------------------------------------------------------------
__global__ __launch_bounds__(128, 3) void edge_kernel(
    const float* __restrict__ ef, const int* __restrict__ src,
    const int* __restrict__ dst,  const float* __restrict__ We,
    const float* __restrict__ g)
{
    // Pre-split B fragments: [ks][n][lane] -> {bhi0, bhi1, blo0, blo1}
    __shared__ uint4 sB[4 * 16 * 32];   // 32 KB

    const int tid = threadIdx.x;
    for (int i = tid; i < 2048; i += 128) {
        const int lane = i & 31, n = (i >> 5) & 15, ks = i >> 9;
        const int k0 = 16*ks + 2*(lane & 3);
        const int c  = 8*n + (lane >> 2);
        const float v00 = We[(k0+0)*HID + c], v01 = We[(k0+1)*HID + c];
        const float v10 = We[(k0+8)*HID + c], v11 = We[(k0+9)*HID + c];
        unsigned h0, l0, h1, l1;
        split2(make_float2(v00, v01), h0, l0);
        split2(make_float2(v10, v11), h1, l1);
        sB[i] = make_uint4(h0, h1, l0, l1);
    }
    __syncthreads();

    const int w = tid >> 5, lane = tid & 31;
    const int gid = lane >> 2, tig = lane & 3;

    // per-lane gamma pairs for cols 8n + 2*tig + {0,1}
    float2 ge[16];
    #pragma unroll
    for (int n = 0; n < 16; n++) ge[n] = *(const float2*)(g + 8*n + 2*tig);

    const float2* ef2 = (const float2*)ef;
    const int nTiles = N_EDGES / 16;      // 50000, exact
    const int nwarp  = gridDim.x * 4;

    for (int t = blockIdx.x * 4 + w; t < nTiles; t += nwarp) {
        const int e0 = t * 16;

        float d[16][4];
        #pragma unroll
        for (int n = 0; n < 16; n++) { d[n][0]=0.f; d[n][1]=0.f; d[n][2]=0.f; d[n][3]=0.f; }

        #pragma unroll
        for (int ks = 0; ks < 4; ks++) {
            // A fragments: rows e0+gid / e0+gid+8, k-chunk 16ks
            const float2 f0 = ef2[(size_t)(e0 + gid    ) * 32 + 8*ks + tig    ];
            const float2 f1 = ef2[(size_t)(e0 + gid + 8) * 32 + 8*ks + tig    ];
            const float2 f2 = ef2[(size_t)(e0 + gid    ) * 32 + 8*ks + tig + 4];
            const float2 f3 = ef2[(size_t)(e0 + gid + 8) * 32 + 8*ks + tig + 4];
            unsigned ah0, al0, ah1, al1, ah2, al2, ah3, al3;
            split2(f0, ah0, al0); split2(f1, ah1, al1);
            split2(f2, ah2, al2); split2(f3, ah3, al3);

            const uint4* sBk = &sB[ks * 512 + lane];
            #pragma unroll
            for (int n = 0; n < 16; n++) {
                const uint4 bb = sBk[n * 32];
                mma_bf16(d[n], ah0, ah1, ah2, ah3, bb.x, bb.y);  // hi*hi
                mma_bf16(d[n], ah0, ah1, ah2, ah3, bb.z, bb.w);  // hi*lo
                mma_bf16(d[n], al0, al1, al2, al3, bb.x, bb.y);  // lo*hi
            }
        }

        // LN stats per edge row (quad-reduce: lanes sharing gid)
        float s0 = 0.f, q0 = 0.f, s1 = 0.f, q1 = 0.f;
        #pragma unroll
        for (int n = 0; n < 16; n++) {
            s0 += d[n][0] + d[n][1];
            q0 += d[n][0]*d[n][0] + d[n][1]*d[n][1];
            s1 += d[n][2] + d[n][3];
            q1 += d[n][2]*d[n][2] + d[n][3]*d[n][3];
        }
        s0 += __shfl_xor_sync(0xffffffffu, s0, 1); s0 += __shfl_xor_sync(0xffffffffu, s0, 2);
        q0 += __shfl_xor_sync(0xffffffffu, q0, 1); q0 += __shfl_xor_sync(0xffffffffu, q0, 2);
        s1 += __shfl_xor_sync(0xffffffffu, s1, 1); s1 += __shfl_xor_sync(0xffffffffu, s1, 2);
        q1 += __shfl_xor_sync(0xffffffffu, q1, 1); q1 += __shfl_xor_sync(0xffffffffu, q1, 2);

        const float mu0   = s0 * (1.f / HID);
        const float rstd0 = rsqrtf(q0 * (1.f / HID) - mu0*mu0 + EPS);
        const float mu1   = s1 * (1.f / HID);
        const float rstd1 = rsqrtf(q1 * (1.f / HID) - mu1*mu1 + EPS);

        const int er0 = e0 + gid, er1 = e0 + gid + 8;
        const int sv0 = src[er0], dv0 = dst[er0];
        const int sv1 = src[er1], dv1 = dst[er1];
        const float2* hv0 = (const float2*)g_hv + (size_t)sv0 * 64 + tig;
        const float2* hv1 = (const float2*)g_hv + (size_t)sv1 * 64 + tig;
        float* o0 = g_h + (size_t)dv0 * HID + 2*tig;
        float* o1 = g_h + (size_t)dv1 * HID + 2*tig;

        #pragma unroll
        for (int n = 0; n < 16; n++) {
            const float e00 = __expf((d[n][0] - mu0) * rstd0 * ge[n].x);
            const float e01 = __expf((d[n][1] - mu0) * rstd0 * ge[n].y);
            const float e10 = __expf((d[n][2] - mu1) * rstd1 * ge[n].x);
            const float e11 = __expf((d[n][3] - mu1) * rstd1 * ge[n].y);
            const float2 h0 = hv0[4*n];
            const float2 h1 = hv1[4*n];
            red_add_v2(o0 + 8*n, h0.x * e00, h0.y * e01);
            red_add_v2(o1 + 8*n, h1.x * e10, h1.y * e11);
        }
    }
}

// ---------------------------------------------------------------------------
// Kernel 3: out = LayerNorm(GELU(h @ W_out))
// ---------------------------------------------------------------------------
__global__ __launch_bounds__(256) void out_kernel(
    const float* __restrict__ Wo, const float* __restrict__ g,
    const float* __restrict__ b,  float* __restrict__ out)
{
    __shared__ float sH [16 * HID];        // 8 KB
    __shared__ float sWo[HID * OUT_DIM];   // 8 KB

    const int tid = threadIdx.x;
    const int n0  = blockIdx.x * 16;
    {
        const float4* hv4 = (const float4*)(g_h + (size_t)n0 * HID);
        float4* sH4 = (float4*)sH;
        #pragma unroll
        for (int i = tid; i < 512; i += 256) sH4[i] = hv4[i];
        const float4* wv4 = (const float4*)Wo;
        float4* sW4 = (float4*)sWo;
        #pragma unroll
        for (int i = tid; i < 512; i += 256) sW4[i] = wv4[i];
    }
    __syncthreads();

    const int n = tid >> 4, c = tid & 15;
    float acc = 0.f;
    const float4* sHn = (const float4*)(sH + n * HID);
    #pragma unroll 4
    for (int k4 = 0; k4 < HID / 4; k4++) {
        const float4 a = sHn[k4];
        acc += a.x * sWo[(4*k4+0)*OUT_DIM + c];
        acc += a.y * sWo[(4*k4+1)*OUT_DIM + c];
        acc += a.z * sWo[(4*k4+2)*OUT_DIM + c];
        acc += a.w * sWo[(4*k4+3)*OUT_DIM + c];
    }

    const float v = gelu_exact(acc);
    float s = v, s2 = v * v;
    #pragma unroll
    for (int off = 8; off; off >>= 1) {
        s  += __shfl_xor_sync(0xffffffffu, s,  off);
        s2 += __shfl_xor_sync(0xffffffffu, s2, off);
    }
    const float mu   = s * (1.f / OUT_DIM);
    const float rstd = rsqrtf(s2 * (1.f / OUT_DIM) - mu * mu + EPS);
    out[(size_t)(n0 + n) * OUT_DIM + c] = (v - mu) * rstd * g[c] + b[c];
}

// ---------------------------------------------------------------------------
extern "C" void kernel_launch(void* const* d_in, const int* in_sizes, int n_in,
                              void* d_out, int out_size) {
    const float* node_feats = (const float*)d_in[0];
    const float* edge_feats = (const float*)d_in[1];
    const int*   src        = (const int*)  d_in[2];
    const int*   dst        = (const int*)  d_in[3];
    const float* W_node     = (const float*)d_in[4];
    const float* g_node     = (const float*)d_in[5];
    const float* b_node     = (const float*)d_in[6];
    const float* W_edge     = (const float*)d_in[7];
    const float* g_edge     = (const float*)d_in[8];
    const float* b_edge     = (const float*)d_in[9];
    const float* W_out      = (const float*)d_in[10];
    const float* g_out      = (const float*)d_in[11];
    const float* b_out      = (const float*)d_in[12];
    float* out = (float*)d_out;

    node_proj_kernel<<<N_NODES / 16, 128>>>(node_feats, W_node, g_node, b_node, b_edge);
    edge_kernel<<<444, 128>>>(edge_feats, src, dst, W_edge, g_edge);
    out_kernel<<<N_NODES / 16, 256>>>(W_out, g_out, b_out, out);
}